// round 1
// baseline (speedup 1.0000x reference)
#include <cuda_runtime.h>
#include <math.h>

#define SS 128
#define BB 128
#define VV 10000
#define HH 512
#define EE 512

// ---------------- scratch (device globals: no allocations allowed) ----------
__device__ float g_P[VV * HH];        // scale * emb @ W0_x^T   (20.5 MB)
__device__ float g_W0h_t[HH * HH];    // k-major transpose of W0[:, :H]
__device__ float g_Wlh_t[HH * HH];    // k-major transpose of Wl[0][:, :H]
__device__ float g_Wlx_t[HH * HH];    // k-major transpose of Wl[0][:, H:]
__device__ float g_h0[2][BB * HH];    // ping-pong layer-0 hidden
__device__ float g_h1[2][BB * HH];    // ping-pong layer-1 hidden
__device__ float g_tops[SS * BB * HH];// layer-1 outputs over time (32 MB)

// ---------------- weight prep -----------------------------------------------
__global__ void prep_weights(const float* __restrict__ W0,
                             const float* __restrict__ Wl) {
    int idx = blockIdx.x * blockDim.x + threadIdx.x;
    if (idx >= HH * HH) return;
    int k = idx / HH;
    int c = idx % HH;
    g_W0h_t[k * HH + c] = W0[c * (HH + EE) + k];
    g_Wlh_t[k * HH + c] = Wl[c * (2 * HH) + k];
    g_Wlx_t[k * HH + c] = Wl[c * (2 * HH) + HH + k];
}

__global__ void init_h(const float* __restrict__ hidden) {
    int i = blockIdx.x * blockDim.x + threadIdx.x;
    if (i < BB * HH) {
        g_h0[0][i] = hidden[i];
        g_h1[0][i] = hidden[BB * HH + i];
    }
}

// ---------------- generic NT SGEMM: C[m,n] = sum_k A[m,k]*Bm[n,k] (+bias) ----
// BM=BN=128, BK=8, 256 threads, 8x8 microtile.
template <bool HAS_BIAS>
__global__ __launch_bounds__(256)
void sgemm_nt(int M, int N, int K,
              const float* __restrict__ A, int lda, float ascale,
              const float* __restrict__ Bm, int ldb,
              float* __restrict__ C, int ldc,
              const float* __restrict__ bias) {
    __shared__ float As[8][128];
    __shared__ float Bs[8][128];

    const int tid = threadIdx.x;
    const int m_base = blockIdx.y * 128;
    const int n_base = blockIdx.x * 128;

    const int lr = tid >> 1;         // 0..127  (row within tile)
    const int lc = (tid & 1) * 4;    // 0 or 4  (k offset)
    const bool a_ok = (m_base + lr) < M;
    const bool b_ok = (n_base + lr) < N;
    const float* Aptr = A + (long long)(m_base + lr) * lda + lc;
    const float* Bptr = Bm + (long long)(n_base + lr) * ldb + lc;

    const int tx = tid & 15;   // n micro index
    const int ty = tid >> 4;   // m micro index

    float acc[8][8];
#pragma unroll
    for (int i = 0; i < 8; i++)
#pragma unroll
        for (int j = 0; j < 8; j++) acc[i][j] = 0.0f;

    for (int k0 = 0; k0 < K; k0 += 8) {
        float4 av = make_float4(0.f, 0.f, 0.f, 0.f);
        float4 bv = make_float4(0.f, 0.f, 0.f, 0.f);
        if (a_ok) av = *reinterpret_cast<const float4*>(Aptr + k0);
        if (b_ok) bv = *reinterpret_cast<const float4*>(Bptr + k0);
        av.x *= ascale; av.y *= ascale; av.z *= ascale; av.w *= ascale;

        __syncthreads();
        As[lc + 0][lr] = av.x;
        As[lc + 1][lr] = av.y;
        As[lc + 2][lr] = av.z;
        As[lc + 3][lr] = av.w;
        Bs[lc + 0][lr] = bv.x;
        Bs[lc + 1][lr] = bv.y;
        Bs[lc + 2][lr] = bv.z;
        Bs[lc + 3][lr] = bv.w;
        __syncthreads();

#pragma unroll
        for (int k = 0; k < 8; k++) {
            float a[8], b[8];
            *reinterpret_cast<float4*>(&a[0]) =
                *reinterpret_cast<const float4*>(&As[k][ty * 8]);
            *reinterpret_cast<float4*>(&a[4]) =
                *reinterpret_cast<const float4*>(&As[k][ty * 8 + 4]);
            *reinterpret_cast<float4*>(&b[0]) =
                *reinterpret_cast<const float4*>(&Bs[k][tx * 8]);
            *reinterpret_cast<float4*>(&b[4]) =
                *reinterpret_cast<const float4*>(&Bs[k][tx * 8 + 4]);
#pragma unroll
            for (int i = 0; i < 8; i++)
#pragma unroll
                for (int j = 0; j < 8; j++) acc[i][j] += a[i] * b[j];
        }
    }

    // epilogue
#pragma unroll
    for (int i = 0; i < 8; i++) {
        int m = m_base + ty * 8 + i;
        if (m >= M) continue;
        float* crow = C + (long long)m * ldc;
#pragma unroll
        for (int j0 = 0; j0 < 8; j0 += 4) {
            int n = n_base + tx * 8 + j0;
            if (n + 3 < N) {
                float4 v;
                v.x = acc[i][j0 + 0];
                v.y = acc[i][j0 + 1];
                v.z = acc[i][j0 + 2];
                v.w = acc[i][j0 + 3];
                if (HAS_BIAS) {
                    const float4 bb = *reinterpret_cast<const float4*>(bias + n);
                    v.x += bb.x; v.y += bb.y; v.z += bb.z; v.w += bb.w;
                }
                *reinterpret_cast<float4*>(crow + n) = v;
            } else {
#pragma unroll
                for (int j = 0; j < 4; j++) {
                    int nn = n + j;
                    if (nn < N)
                        crow[nn] = acc[i][j0 + j] + (HAS_BIAS ? bias[nn] : 0.0f);
                }
            }
        }
    }
}

// ---------------- recurrent step kernels -------------------------------------
// grid = 128 CTAs, block = 128 threads. tile = 8 rows x 64 cols, 4 cols/thread.

__global__ __launch_bounds__(128)
void rnn_layer0(int parity, int s, const int* __restrict__ inputs,
                const float* __restrict__ b0) {
    const int tid = threadIdx.x;
    const int r = ((blockIdx.x >> 3) << 3) + (tid >> 4);
    const int c = ((blockIdx.x & 7) << 6) + ((tid & 15) << 2);

    const float* __restrict__ hr = g_h0[parity] + r * HH;
    float ax = 0.f, ay = 0.f, az = 0.f, aw = 0.f;

#pragma unroll 4
    for (int k = 0; k < HH; k += 4) {
        float4 a = *reinterpret_cast<const float4*>(hr + k);
#pragma unroll
        for (int i = 0; i < 4; i++) {
            float av = (i == 0) ? a.x : (i == 1) ? a.y : (i == 2) ? a.z : a.w;
            float4 w = *reinterpret_cast<const float4*>(g_W0h_t + (k + i) * HH + c);
            ax += av * w.x; ay += av * w.y; az += av * w.z; aw += av * w.w;
        }
    }

    const int t = inputs[s * BB + r];
    const float4 p = *reinterpret_cast<const float4*>(g_P + t * HH + c);
    const float4 bb = *reinterpret_cast<const float4*>(b0 + c);

    float4 out;
    out.x = tanhf(ax + p.x + bb.x);
    out.y = tanhf(ay + p.y + bb.y);
    out.z = tanhf(az + p.z + bb.z);
    out.w = tanhf(aw + p.w + bb.w);
    *reinterpret_cast<float4*>(g_h0[parity ^ 1] + r * HH + c) = out;
}

__global__ __launch_bounds__(128)
void rnn_layer1(int parity, int s, const float* __restrict__ bl) {
    const int tid = threadIdx.x;
    const int r = ((blockIdx.x >> 3) << 3) + (tid >> 4);
    const int c = ((blockIdx.x & 7) << 6) + ((tid & 15) << 2);

    const float* __restrict__ h1r = g_h1[parity] + r * HH;       // previous h1
    const float* __restrict__ h0r = g_h0[parity ^ 1] + r * HH;   // current layer-0 out
    float ax = 0.f, ay = 0.f, az = 0.f, aw = 0.f;

#pragma unroll 4
    for (int k = 0; k < HH; k += 4) {
        float4 a = *reinterpret_cast<const float4*>(h1r + k);
#pragma unroll
        for (int i = 0; i < 4; i++) {
            float av = (i == 0) ? a.x : (i == 1) ? a.y : (i == 2) ? a.z : a.w;
            float4 w = *reinterpret_cast<const float4*>(g_Wlh_t + (k + i) * HH + c);
            ax += av * w.x; ay += av * w.y; az += av * w.z; aw += av * w.w;
        }
    }
#pragma unroll 4
    for (int k = 0; k < HH; k += 4) {
        float4 a = *reinterpret_cast<const float4*>(h0r + k);
#pragma unroll
        for (int i = 0; i < 4; i++) {
            float av = (i == 0) ? a.x : (i == 1) ? a.y : (i == 2) ? a.z : a.w;
            float4 w = *reinterpret_cast<const float4*>(g_Wlx_t + (k + i) * HH + c);
            ax += av * w.x; ay += av * w.y; az += av * w.z; aw += av * w.w;
        }
    }

    const float4 bb = *reinterpret_cast<const float4*>(bl + c);
    float4 out;
    out.x = tanhf(ax + bb.x);
    out.y = tanhf(ay + bb.y);
    out.z = tanhf(az + bb.z);
    out.w = tanhf(aw + bb.w);
    *reinterpret_cast<float4*>(g_h1[parity ^ 1] + r * HH + c) = out;
    *reinterpret_cast<float4*>(g_tops + (long long)s * BB * HH + r * HH + c) = out;
}

// ---------------- final hidden copy ------------------------------------------
__global__ void write_hfinal(float* __restrict__ out) {
    int i = blockIdx.x * blockDim.x + threadIdx.x;
    if (i < BB * HH) {
        out[i] = g_h0[0][i];
        out[BB * HH + i] = g_h1[0][i];
    }
}

// ---------------- launch ------------------------------------------------------
extern "C" void kernel_launch(void* const* d_in, const int* in_sizes, int n_in,
                              void* d_out, int out_size) {
    const int*   inputs = (const int*)  d_in[0];  // [S,B]
    const float* hidden = (const float*)d_in[1];  // [L,B,H]
    const float* emb    = (const float*)d_in[2];  // [V,E]
    const float* W0     = (const float*)d_in[3];  // [H, H+E]
    const float* b0     = (const float*)d_in[4];  // [H]
    const float* Wl     = (const float*)d_in[5];  // [1, H, 2H]
    const float* bl     = (const float*)d_in[6];  // [1, H]
    const float* Wout   = (const float*)d_in[7];  // [V, H]
    const float* bout   = (const float*)d_in[8];  // [V]

    float* logits = (float*)d_out;                           // [S,B,V]
    float* hfin   = (float*)d_out + (long long)SS * BB * VV; // [L,B,H]

    float *pP = nullptr, *pTops = nullptr;
    cudaGetSymbolAddress((void**)&pP, g_P);
    cudaGetSymbolAddress((void**)&pTops, g_tops);

    // 1. weight transposes + hidden init
    prep_weights<<<(HH * HH + 255) / 256, 256>>>(W0, Wl);
    init_h<<<(BB * HH + 255) / 256, 256>>>(hidden);

    // 2. P = scale * emb @ W0_x^T   (M=V, N=H, K=E)
    {
        const float ascale = 22.62741699796952f;  // sqrt(512)
        dim3 grid((HH + 127) / 128, (VV + 127) / 128);
        sgemm_nt<false><<<grid, 256>>>(VV, HH, EE,
                                       emb, EE, ascale,
                                       W0 + HH, HH + EE,
                                       pP, HH, nullptr);
    }

    // 3. recurrence: 128 sequential steps, 2 layers each
    for (int s = 0; s < SS; s++) {
        int p = s & 1;
        rnn_layer0<<<128, 128>>>(p, s, inputs, b0);
        rnn_layer1<<<128, 128>>>(p, s, bl);
    }

    // 4. logits = tops @ Wout^T + bout   (M=S*B, N=V, K=H)
    {
        dim3 grid((VV + 127) / 128, (SS * BB + 127) / 128);
        sgemm_nt<true><<<grid, 256>>>(SS * BB, VV, HH,
                                      pTops, HH, 1.0f,
                                      Wout, HH,
                                      logits, VV, bout);
    }

    // 5. final hidden state
    write_hfinal<<<(BB * HH + 255) / 256, 256>>>(hfin);
}

// round 3
// speedup vs baseline: 1.1280x; 1.1280x over previous
#include <cuda_runtime.h>
#include <cuda_bf16.h>
#include <math.h>
#include <stdint.h>

#define SS 128
#define BB 128
#define VV 10000
#define HH 512
#define EE 512
#define KDIM 512

// ---------------- scratch (device globals: no allocations allowed) ----------
__device__ float g_P[VV * HH];         // scale * emb @ W0_x^T
__device__ float g_W0h_t[HH * HH];     // k-major transpose of W0[:, :H]
__device__ float g_Wlh_t[HH * HH];     // k-major transpose of Wl[0][:, :H]
__device__ float g_Wlx_t[HH * HH];     // k-major transpose of Wl[0][:, H:]
__device__ float g_h0[2][BB * HH];
__device__ float g_h1[2][BB * HH];
// bf16 hi/lo split operands for tensor GEMMs
__device__ __nv_bfloat16 g_Thi[SS * BB * HH];
__device__ __nv_bfloat16 g_Tlo[SS * BB * HH];
__device__ __nv_bfloat16 g_Whi[VV * HH];
__device__ __nv_bfloat16 g_Wlo[VV * HH];
__device__ __nv_bfloat16 g_Ehi[VV * EE];
__device__ __nv_bfloat16 g_Elo[VV * EE];
__device__ __nv_bfloat16 g_Xhi[HH * EE];
__device__ __nv_bfloat16 g_Xlo[HH * EE];

// ============================ helpers ========================================
__device__ __forceinline__ uint32_t smem_u32(const void* p) {
    uint32_t a;
    asm("{ .reg .u64 t; cvta.to.shared.u64 t, %1; cvt.u32.u64 %0, t; }"
        : "=r"(a) : "l"(p));
    return a;
}

__device__ __forceinline__ void ldm_x4(uint32_t addr, uint32_t r[4]) {
    asm volatile("ldmatrix.sync.aligned.m8n8.x4.shared.b16 {%0,%1,%2,%3}, [%4];"
                 : "=r"(r[0]), "=r"(r[1]), "=r"(r[2]), "=r"(r[3]) : "r"(addr));
}

__device__ __forceinline__ void mma_bf16(float c[4], const uint32_t a[4],
                                         uint32_t b0, uint32_t b1) {
    asm volatile(
        "mma.sync.aligned.m16n8k16.row.col.f32.bf16.bf16.f32 "
        "{%0,%1,%2,%3}, {%4,%5,%6,%7}, {%8,%9}, {%0,%1,%2,%3};"
        : "+f"(c[0]), "+f"(c[1]), "+f"(c[2]), "+f"(c[3])
        : "r"(a[0]), "r"(a[1]), "r"(a[2]), "r"(a[3]), "r"(b0), "r"(b1));
}

// =================== bf16-split HMMA GEMM ====================================
// C[m,n] = sum_k A[m,k]*B[n,k] (+bias), K = 512.
// 3-pass split: Ahi*Bhi + Ahi*Blo + Alo*Bhi, fp32 accumulate.
// Block tile 128x128, BK=32, 8 warps (4x2), warp tile 32x64. cp.async 2-stage.

#define BK 32
#define ROWB 80                 // padded smem row stride (bytes) = 40 bf16
#define TILE_SB (128 * ROWB)    // 10240 B per tile
#define STAGE_SB (4 * TILE_SB)  // Ahi,Alo,Bhi,Blo = 40960 B
#define GEMM_SMEM (2 * STAGE_SB)
#define KT_N (KDIM / BK)        // 16

__global__ __launch_bounds__(256, 1)
void gemm_hmma(const __nv_bfloat16* __restrict__ Ahi,
               const __nv_bfloat16* __restrict__ Alo,
               const __nv_bfloat16* __restrict__ Bhi,
               const __nv_bfloat16* __restrict__ Blo,
               int M, int N, float* __restrict__ C, int ldc,
               const float* __restrict__ bias) {
    extern __shared__ char smem[];
    const uint32_t sb = smem_u32(smem);
    const int tid = threadIdx.x;
    const int wid = tid >> 5, lid = tid & 31;
    const int wm = wid & 3, wn = wid >> 2;
    const int nb = blockIdx.x, mb = blockIdx.y;

    const __nv_bfloat16* __restrict__ srcs[4] = {Ahi, Alo, Bhi, Blo};

    float acc[2][8][4];
#pragma unroll
    for (int i = 0; i < 2; i++)
#pragma unroll
        for (int j = 0; j < 8; j++)
#pragma unroll
            for (int q = 0; q < 4; q++) acc[i][j][q] = 0.0f;

    // ---- stage loader ----
    auto load_stage = [&](int st, int kt) {
#pragma unroll
        for (int t = 0; t < 4; t++) {
#pragma unroll
            for (int i = 0; i < 2; i++) {
                const int idx = tid + i * 256;         // 0..511
                const int row = idx >> 2, ch = idx & 3;
                const long long grow =
                    (t < 2) ? (long long)mb * 128 + row : (long long)nb * 128 + row;
                const bool ok = (t < 2) ? (grow < M) : (grow < N);
                const __nv_bfloat16* src = srcs[t] + grow * KDIM + kt * BK + ch * 8;
                const uint32_t dst = sb + st * STAGE_SB + t * TILE_SB + row * ROWB + ch * 16;
                const int sz = ok ? 16 : 0;
                asm volatile("cp.async.cg.shared.global [%0], [%1], 16, %2;"
                             :: "r"(dst), "l"(src), "r"(sz) : "memory");
            }
        }
    };

    // ldmatrix lane addressing pieces
    const int lr = lid & 15;          // row within 16-row fragment
    const int lc = lid >> 4;          // 0/1 -> +16B k chunk

    load_stage(0, 0);
    asm volatile("cp.async.commit_group;" ::: "memory");

    for (int kt = 0; kt < KT_N; kt++) {
        const int st = kt & 1;
        if (kt + 1 < KT_N) {
            load_stage(st ^ 1, kt + 1);
            asm volatile("cp.async.commit_group;" ::: "memory");
            asm volatile("cp.async.wait_group 1;" ::: "memory");
        } else {
            asm volatile("cp.async.wait_group 0;" ::: "memory");
        }
        __syncthreads();

        const uint32_t stg = sb + st * STAGE_SB;
        const uint32_t aBaseHi = stg + 0 * TILE_SB;
        const uint32_t aBaseLo = stg + 1 * TILE_SB;
        const uint32_t bBaseHi = stg + 2 * TILE_SB;
        const uint32_t bBaseLo = stg + 3 * TILE_SB;

#pragma unroll
        for (int k16 = 0; k16 < 2; k16++) {
            const uint32_t koff = k16 * 32 + lc * 16;   // bytes within row

            uint32_t ahi[2][4], alo[2][4];
#pragma unroll
            for (int mf = 0; mf < 2; mf++) {
                const uint32_t roff = (uint32_t)(wm * 32 + mf * 16 + lr) * ROWB + koff;
                ldm_x4(aBaseHi + roff, ahi[mf]);
                ldm_x4(aBaseLo + roff, alo[mf]);
            }
#pragma unroll
            for (int reg = 0; reg < 4; reg++) {
                const uint32_t roff = (uint32_t)(wn * 64 + reg * 16 + lr) * ROWB + koff;
                uint32_t bh[4], blo[4];
                ldm_x4(bBaseHi + roff, bh);
                ldm_x4(bBaseLo + roff, blo);
                // frag n(reg*2+0): b0=r0,b1=r2 ; frag n(reg*2+1): b0=r1,b1=r3
#pragma unroll
                for (int mf = 0; mf < 2; mf++) {
                    mma_bf16(acc[mf][reg * 2 + 0], ahi[mf], bh[0], bh[2]);
                    mma_bf16(acc[mf][reg * 2 + 0], ahi[mf], blo[0], blo[2]);
                    mma_bf16(acc[mf][reg * 2 + 0], alo[mf], bh[0], bh[2]);
                    mma_bf16(acc[mf][reg * 2 + 1], ahi[mf], bh[1], bh[3]);
                    mma_bf16(acc[mf][reg * 2 + 1], ahi[mf], blo[1], blo[3]);
                    mma_bf16(acc[mf][reg * 2 + 1], alo[mf], bh[1], bh[3]);
                }
            }
        }
        __syncthreads();
    }

    // ---- epilogue ----
    const int lr4 = lid >> 2;
    const int lc2 = (lid & 3) * 2;
#pragma unroll
    for (int mf = 0; mf < 2; mf++) {
#pragma unroll
        for (int nf = 0; nf < 8; nf++) {
            const int m = mb * 128 + wm * 32 + mf * 16 + lr4;
            const int n = nb * 128 + wn * 64 + nf * 8 + lc2;
            if (n >= N) continue;
            float b0 = 0.f, b1 = 0.f;
            if (bias) { b0 = bias[n]; b1 = bias[n + 1]; }
            if (m < M) {
                float2 v = make_float2(acc[mf][nf][0] + b0, acc[mf][nf][1] + b1);
                *reinterpret_cast<float2*>(C + (long long)m * ldc + n) = v;
            }
            if (m + 8 < M) {
                float2 v = make_float2(acc[mf][nf][2] + b0, acc[mf][nf][3] + b1);
                *reinterpret_cast<float2*>(C + (long long)(m + 8) * ldc + n) = v;
            }
        }
    }
}

// ---------------- prep kernels -----------------------------------------------
__global__ void prep_weights(const float* __restrict__ W0,
                             const float* __restrict__ Wl) {
    int idx = blockIdx.x * blockDim.x + threadIdx.x;
    if (idx >= HH * HH) return;
    int k = idx / HH;
    int c = idx % HH;
    g_W0h_t[k * HH + c] = W0[c * (HH + EE) + k];
    g_Wlh_t[k * HH + c] = Wl[c * (2 * HH) + k];
    g_Wlx_t[k * HH + c] = Wl[c * (2 * HH) + HH + k];
    float v = W0[k * (HH + EE) + HH + c];   // row n=k, kcol=c
    __nv_bfloat16 hi = __float2bfloat16(v);
    g_Xhi[k * EE + c] = hi;
    g_Xlo[k * EE + c] = __float2bfloat16(v - __bfloat162float(hi));
}

__global__ void split_arr(const float* __restrict__ src, __nv_bfloat16* __restrict__ hi,
                          __nv_bfloat16* __restrict__ lo, int n, float scale) {
    int i = blockIdx.x * blockDim.x + threadIdx.x;
    if (i >= n) return;
    float v = src[i] * scale;
    __nv_bfloat16 h = __float2bfloat16(v);
    hi[i] = h;
    lo[i] = __float2bfloat16(v - __bfloat162float(h));
}

__global__ void init_h(const float* __restrict__ hidden) {
    int i = blockIdx.x * blockDim.x + threadIdx.x;
    if (i < BB * HH) {
        g_h0[0][i] = hidden[i];
        g_h1[0][i] = hidden[BB * HH + i];
    }
}

// ---------------- recurrent step kernels -------------------------------------
__global__ __launch_bounds__(128)
void rnn_layer0(int parity, int s, const int* __restrict__ inputs,
                const float* __restrict__ b0) {
    const int tid = threadIdx.x;
    const int r = ((blockIdx.x >> 3) << 3) + (tid >> 4);
    const int c = ((blockIdx.x & 7) << 6) + ((tid & 15) << 2);

    const float* __restrict__ hr = g_h0[parity] + r * HH;
    float ax = 0.f, ay = 0.f, az = 0.f, aw = 0.f;
#pragma unroll 4
    for (int k = 0; k < HH; k += 4) {
        float4 a = *reinterpret_cast<const float4*>(hr + k);
#pragma unroll
        for (int i = 0; i < 4; i++) {
            float av = (i == 0) ? a.x : (i == 1) ? a.y : (i == 2) ? a.z : a.w;
            float4 w = *reinterpret_cast<const float4*>(g_W0h_t + (k + i) * HH + c);
            ax += av * w.x; ay += av * w.y; az += av * w.z; aw += av * w.w;
        }
    }
    const int t = inputs[s * BB + r];
    const float4 p = *reinterpret_cast<const float4*>(g_P + t * HH + c);
    const float4 bb = *reinterpret_cast<const float4*>(b0 + c);
    float4 out;
    out.x = tanhf(ax + p.x + bb.x);
    out.y = tanhf(ay + p.y + bb.y);
    out.z = tanhf(az + p.z + bb.z);
    out.w = tanhf(aw + p.w + bb.w);
    *reinterpret_cast<float4*>(g_h0[parity ^ 1] + r * HH + c) = out;
}

__global__ __launch_bounds__(128)
void rnn_layer1(int parity, int s, const float* __restrict__ bl) {
    const int tid = threadIdx.x;
    const int r = ((blockIdx.x >> 3) << 3) + (tid >> 4);
    const int c = ((blockIdx.x & 7) << 6) + ((tid & 15) << 2);

    const float* __restrict__ h1r = g_h1[parity] + r * HH;
    const float* __restrict__ h0r = g_h0[parity ^ 1] + r * HH;
    float ax = 0.f, ay = 0.f, az = 0.f, aw = 0.f;
#pragma unroll 4
    for (int k = 0; k < HH; k += 4) {
        float4 a = *reinterpret_cast<const float4*>(h1r + k);
#pragma unroll
        for (int i = 0; i < 4; i++) {
            float av = (i == 0) ? a.x : (i == 1) ? a.y : (i == 2) ? a.z : a.w;
            float4 w = *reinterpret_cast<const float4*>(g_Wlh_t + (k + i) * HH + c);
            ax += av * w.x; ay += av * w.y; az += av * w.z; aw += av * w.w;
        }
    }
#pragma unroll 4
    for (int k = 0; k < HH; k += 4) {
        float4 a = *reinterpret_cast<const float4*>(h0r + k);
#pragma unroll
        for (int i = 0; i < 4; i++) {
            float av = (i == 0) ? a.x : (i == 1) ? a.y : (i == 2) ? a.z : a.w;
            float4 w = *reinterpret_cast<const float4*>(g_Wlx_t + (k + i) * HH + c);
            ax += av * w.x; ay += av * w.y; az += av * w.z; aw += av * w.w;
        }
    }
    const float4 bb = *reinterpret_cast<const float4*>(bl + c);
    float4 out;
    out.x = tanhf(ax + bb.x);
    out.y = tanhf(ay + bb.y);
    out.z = tanhf(az + bb.z);
    out.w = tanhf(aw + bb.w);
    *reinterpret_cast<float4*>(g_h1[parity ^ 1] + r * HH + c) = out;

    const long long tb = (long long)s * BB * HH + r * HH + c;
    float v[4] = {out.x, out.y, out.z, out.w};
#pragma unroll
    for (int j = 0; j < 4; j++) {
        __nv_bfloat16 h = __float2bfloat16(v[j]);
        g_Thi[tb + j] = h;
        g_Tlo[tb + j] = __float2bfloat16(v[j] - __bfloat162float(h));
    }
}

__global__ void write_hfinal(float* __restrict__ out) {
    int i = blockIdx.x * blockDim.x + threadIdx.x;
    if (i < BB * HH) {
        out[i] = g_h0[0][i];
        out[BB * HH + i] = g_h1[0][i];
    }
}

// ---------------- launch ------------------------------------------------------
extern "C" void kernel_launch(void* const* d_in, const int* in_sizes, int n_in,
                              void* d_out, int out_size) {
    const int*   inputs = (const int*)  d_in[0];
    const float* hidden = (const float*)d_in[1];
    const float* emb    = (const float*)d_in[2];
    const float* W0     = (const float*)d_in[3];
    const float* b0     = (const float*)d_in[4];
    const float* Wl     = (const float*)d_in[5];
    const float* bl     = (const float*)d_in[6];
    const float* Wout   = (const float*)d_in[7];
    const float* bout   = (const float*)d_in[8];

    float* logits = (float*)d_out;
    float* hfin   = (float*)d_out + (long long)SS * BB * VV;

    static bool attr_set = false;
    if (!attr_set) {
        cudaFuncSetAttribute(gemm_hmma, cudaFuncAttributeMaxDynamicSharedMemorySize,
                             GEMM_SMEM);
        attr_set = true;
    }

    float* pP = nullptr;
    cudaGetSymbolAddress((void**)&pP, g_P);
    __nv_bfloat16 *pThi, *pTlo, *pWhi, *pWlo, *pEhi, *pElo, *pXhi, *pXlo;
    cudaGetSymbolAddress((void**)&pThi, g_Thi);
    cudaGetSymbolAddress((void**)&pTlo, g_Tlo);
    cudaGetSymbolAddress((void**)&pWhi, g_Whi);
    cudaGetSymbolAddress((void**)&pWlo, g_Wlo);
    cudaGetSymbolAddress((void**)&pEhi, g_Ehi);
    cudaGetSymbolAddress((void**)&pElo, g_Elo);
    cudaGetSymbolAddress((void**)&pXhi, g_Xhi);
    cudaGetSymbolAddress((void**)&pXlo, g_Xlo);

    const float scale = 22.62741699796952f;  // sqrt(512)

    prep_weights<<<(HH * HH + 255) / 256, 256>>>(W0, Wl);
    split_arr<<<(VV * EE + 255) / 256, 256>>>(emb, pEhi, pElo, VV * EE, scale);
    split_arr<<<(VV * HH + 255) / 256, 256>>>(Wout, pWhi, pWlo, VV * HH, 1.0f);
    init_h<<<(BB * HH + 255) / 256, 256>>>(hidden);

    // P = scale*emb @ W0x^T  (M=10000, N=512, K=512)
    {
        dim3 grid((HH + 127) / 128, (VV + 127) / 128);
        gemm_hmma<<<grid, 256, GEMM_SMEM>>>(pEhi, pElo, pXhi, pXlo,
                                            VV, HH, pP, HH, nullptr);
    }

    // recurrence
    for (int s = 0; s < SS; s++) {
        int p = s & 1;
        rnn_layer0<<<128, 128>>>(p, s, inputs, b0);
        rnn_layer1<<<128, 128>>>(p, s, bl);
    }

    // logits = tops @ Wout^T + bout  (M=16384, N=10000, K=512)
    {
        dim3 grid((VV + 127) / 128, (SS * BB + 127) / 128);
        gemm_hmma<<<grid, 256, GEMM_SMEM>>>(pThi, pTlo, pWhi, pWlo,
                                            SS * BB, VV, logits, VV, bout);
    }

    write_hfinal<<<(BB * HH + 255) / 256, 256>>>(hfin);
}

// round 5
// speedup vs baseline: 4.5743x; 4.0553x over previous
#include <cuda_runtime.h>
#include <cuda_bf16.h>
#include <math.h>
#include <stdint.h>

#define SS 128
#define BB 128
#define VV 10000
#define HH 512
#define EE 512
#define KDIM 512

// ---------------- scratch (device globals: no allocations allowed) ----------
__device__ float g_P[VV * HH];         // scale * emb @ W0_x^T
__device__ float g_h0[2][BB * HH];     // ping-pong layer-0 hidden
__device__ float g_h1[2][BB * HH];     // ping-pong layer-1 hidden
__device__ unsigned int g_sync;        // grid barrier counter
// bf16 hi/lo split operands for tensor GEMMs
__device__ __nv_bfloat16 g_Thi[SS * BB * HH];
__device__ __nv_bfloat16 g_Tlo[SS * BB * HH];
__device__ __nv_bfloat16 g_Whi[VV * HH];
__device__ __nv_bfloat16 g_Wlo[VV * HH];
__device__ __nv_bfloat16 g_Ehi[VV * EE];
__device__ __nv_bfloat16 g_Elo[VV * EE];
__device__ __nv_bfloat16 g_Xhi[HH * EE];
__device__ __nv_bfloat16 g_Xlo[HH * EE];

// ============================ helpers ========================================
__device__ __forceinline__ uint32_t smem_u32(const void* p) {
    uint32_t a;
    asm("{ .reg .u64 t; cvta.to.shared.u64 t, %1; cvt.u32.u64 %0, t; }"
        : "=r"(a) : "l"(p));
    return a;
}

__device__ __forceinline__ void ldm_x4(uint32_t addr, uint32_t r[4]) {
    asm volatile("ldmatrix.sync.aligned.m8n8.x4.shared.b16 {%0,%1,%2,%3}, [%4];"
                 : "=r"(r[0]), "=r"(r[1]), "=r"(r[2]), "=r"(r[3]) : "r"(addr));
}

__device__ __forceinline__ void mma_bf16(float c[4], const uint32_t a[4],
                                         uint32_t b0, uint32_t b1) {
    asm volatile(
        "mma.sync.aligned.m16n8k16.row.col.f32.bf16.bf16.f32 "
        "{%0,%1,%2,%3}, {%4,%5,%6,%7}, {%8,%9}, {%0,%1,%2,%3};"
        : "+f"(c[0]), "+f"(c[1]), "+f"(c[2]), "+f"(c[3])
        : "r"(a[0]), "r"(a[1]), "r"(a[2]), "r"(a[3]), "r"(b0), "r"(b1));
}

__device__ __forceinline__ void fma4(float4& acc, const float4& a, const float4& b) {
    acc.x = fmaf(a.x, b.x, acc.x);
    acc.y = fmaf(a.y, b.y, acc.y);
    acc.z = fmaf(a.z, b.z, acc.z);
    acc.w = fmaf(a.w, b.w, acc.w);
}

// =================== bf16-split HMMA GEMM (unchanged, passing) ===============
#define BK 32
#define ROWB 80
#define TILE_SB (128 * ROWB)
#define STAGE_SB (4 * TILE_SB)
#define GEMM_SMEM (2 * STAGE_SB)
#define KT_N (KDIM / BK)

__global__ __launch_bounds__(256, 1)
void gemm_hmma(const __nv_bfloat16* __restrict__ Ahi,
               const __nv_bfloat16* __restrict__ Alo,
               const __nv_bfloat16* __restrict__ Bhi,
               const __nv_bfloat16* __restrict__ Blo,
               int M, int N, float* __restrict__ C, int ldc,
               const float* __restrict__ bias) {
    extern __shared__ char smem[];
    const uint32_t sb = smem_u32(smem);
    const int tid = threadIdx.x;
    const int wid = tid >> 5, lid = tid & 31;
    const int wm = wid & 3, wn = wid >> 2;
    const int nb = blockIdx.x, mb = blockIdx.y;

    const __nv_bfloat16* __restrict__ srcs[4] = {Ahi, Alo, Bhi, Blo};

    float acc[2][8][4];
#pragma unroll
    for (int i = 0; i < 2; i++)
#pragma unroll
        for (int j = 0; j < 8; j++)
#pragma unroll
            for (int q = 0; q < 4; q++) acc[i][j][q] = 0.0f;

    auto load_stage = [&](int st, int kt) {
#pragma unroll
        for (int t = 0; t < 4; t++) {
#pragma unroll
            for (int i = 0; i < 2; i++) {
                const int idx = tid + i * 256;
                const int row = idx >> 2, ch = idx & 3;
                const long long grow =
                    (t < 2) ? (long long)mb * 128 + row : (long long)nb * 128 + row;
                const bool ok = (t < 2) ? (grow < M) : (grow < N);
                const __nv_bfloat16* src = srcs[t] + grow * KDIM + kt * BK + ch * 8;
                const uint32_t dst = sb + st * STAGE_SB + t * TILE_SB + row * ROWB + ch * 16;
                const int sz = ok ? 16 : 0;
                asm volatile("cp.async.cg.shared.global [%0], [%1], 16, %2;"
                             :: "r"(dst), "l"(src), "r"(sz) : "memory");
            }
        }
    };

    const int lr = lid & 15;
    const int lc = lid >> 4;

    load_stage(0, 0);
    asm volatile("cp.async.commit_group;" ::: "memory");

    for (int kt = 0; kt < KT_N; kt++) {
        const int st = kt & 1;
        if (kt + 1 < KT_N) {
            load_stage(st ^ 1, kt + 1);
            asm volatile("cp.async.commit_group;" ::: "memory");
            asm volatile("cp.async.wait_group 1;" ::: "memory");
        } else {
            asm volatile("cp.async.wait_group 0;" ::: "memory");
        }
        __syncthreads();

        const uint32_t stg = sb + st * STAGE_SB;
        const uint32_t aBaseHi = stg + 0 * TILE_SB;
        const uint32_t aBaseLo = stg + 1 * TILE_SB;
        const uint32_t bBaseHi = stg + 2 * TILE_SB;
        const uint32_t bBaseLo = stg + 3 * TILE_SB;

#pragma unroll
        for (int k16 = 0; k16 < 2; k16++) {
            const uint32_t koff = k16 * 32 + lc * 16;

            uint32_t ahi[2][4], alo[2][4];
#pragma unroll
            for (int mf = 0; mf < 2; mf++) {
                const uint32_t roff = (uint32_t)(wm * 32 + mf * 16 + lr) * ROWB + koff;
                ldm_x4(aBaseHi + roff, ahi[mf]);
                ldm_x4(aBaseLo + roff, alo[mf]);
            }
#pragma unroll
            for (int reg = 0; reg < 4; reg++) {
                const uint32_t roff = (uint32_t)(wn * 64 + reg * 16 + lr) * ROWB + koff;
                uint32_t bh[4], bl2[4];
                ldm_x4(bBaseHi + roff, bh);
                ldm_x4(bBaseLo + roff, bl2);
#pragma unroll
                for (int mf = 0; mf < 2; mf++) {
                    mma_bf16(acc[mf][reg * 2 + 0], ahi[mf], bh[0], bh[2]);
                    mma_bf16(acc[mf][reg * 2 + 0], ahi[mf], bl2[0], bl2[2]);
                    mma_bf16(acc[mf][reg * 2 + 0], alo[mf], bh[0], bh[2]);
                    mma_bf16(acc[mf][reg * 2 + 1], ahi[mf], bh[1], bh[3]);
                    mma_bf16(acc[mf][reg * 2 + 1], ahi[mf], bl2[1], bl2[3]);
                    mma_bf16(acc[mf][reg * 2 + 1], alo[mf], bh[1], bh[3]);
                }
            }
        }
        __syncthreads();
    }

    const int lr4 = lid >> 2;
    const int lc2 = (lid & 3) * 2;
#pragma unroll
    for (int mf = 0; mf < 2; mf++) {
#pragma unroll
        for (int nf = 0; nf < 8; nf++) {
            const int m = mb * 128 + wm * 32 + mf * 16 + lr4;
            const int n = nb * 128 + wn * 64 + nf * 8 + lc2;
            if (n >= N) continue;
            float b0 = 0.f, b1 = 0.f;
            if (bias) { b0 = bias[n]; b1 = bias[n + 1]; }
            if (m < M) {
                float2 v = make_float2(acc[mf][nf][0] + b0, acc[mf][nf][1] + b1);
                *reinterpret_cast<float2*>(C + (long long)m * ldc + n) = v;
            }
            if (m + 8 < M) {
                float2 v = make_float2(acc[mf][nf][2] + b0, acc[mf][nf][3] + b1);
                *reinterpret_cast<float2*>(C + (long long)(m + 8) * ldc + n) = v;
            }
        }
    }
}

// =================== persistent recurrence kernel ============================
// 128 CTAs = 4 batch-groups(32 rows) x 32 col-groups(16 cols). 256 threads.
// Weights (W0h, Wlh, Wlx slices) resident in smem for all 128 steps.
// Phase p: compute h0(p) = f(h0(p-1))  AND  h1(p-1) = f(h0(p-1), h1(p-2)).
// One grid barrier per phase (red.release + ld.acquire spin on g_sync).

#define RNN_CTAS 128
#define RNN_THR 256
#define WSTR 516                       // padded weight row stride (floats)
#define HSTR 132                       // padded h-stage row stride (floats)
#define OFF_W0 0
#define OFF_WL (16 * WSTR)
#define OFF_WX (32 * WSTR)
#define OFF_HS (48 * WSTR)
#define RNN_SMEM ((48 * WSTR + 32 * HSTR) * 4)   // 115968 B

__device__ __forceinline__ void grid_bar(unsigned int target) {
    __syncthreads();
    if (threadIdx.x == 0) {
        unsigned int* p = &g_sync;
        asm volatile("red.release.gpu.global.add.u32 [%0], 1;" :: "l"(p) : "memory");
        unsigned int v;
        do {
            asm volatile("ld.acquire.gpu.global.u32 %0, [%1];" : "=r"(v) : "l"(p) : "memory");
        } while (v < target);
    }
    __syncthreads();
}

__global__ __launch_bounds__(RNN_THR, 1)
void rnn_persist(const int* __restrict__ inputs,
                 const float* __restrict__ W0,
                 const float* __restrict__ b0,
                 const float* __restrict__ Wl,
                 const float* __restrict__ bl) {
    extern __shared__ float sm[];
    const int tid = threadIdx.x;
    const int bg = blockIdx.x >> 5;        // batch group: rows [bg*32, bg*32+32)
    const int cg = blockIdx.x & 31;        // col group:  cols [cg*16, cg*16+16)
    const int cbase = cg * 16;

    // ---- load weight slices into smem (once) ----
    for (int i = tid; i < 16 * 512; i += RNN_THR) {
        const int r = i >> 9, k = i & 511;
        const int gc = cbase + r;
        sm[OFF_W0 + r * WSTR + k] = W0[gc * 1024 + k];         // layer0 h-part
        sm[OFF_WL + r * WSTR + k] = Wl[gc * 1024 + k];         // layer1 h1-part
        sm[OFF_WX + r * WSTR + k] = Wl[gc * 1024 + 512 + k];   // layer1 h0-part
    }
    __syncthreads();

    const int c_l = tid & 15;              // local col 0..15
    const int rg = tid >> 4;               // 0..15 -> local rows rg*2, rg*2+1
    const int col = cbase + c_l;
    const int r0 = rg * 2, r1 = rg * 2 + 1;
    const int gb0 = bg * 32 + r0, gb1 = bg * 32 + r1;
    const float b0c = b0[col];
    const float blc = bl[col];
    float* const hs = sm + OFF_HS;

    for (int p = 0; p <= SS; p++) {
        const float* __restrict__ h0old = g_h0[(p + 1) & 1];
        const float* __restrict__ h1prev = g_h1[p & 1];
        float* __restrict__ h0new = g_h0[p & 1];
        float* __restrict__ h1new = g_h1[(p + 1) & 1];

        float4 a00 = make_float4(0, 0, 0, 0), a01 = a00;   // layer0, rows r0/r1
        float4 a10 = a00, a11 = a00;                        // layer1, rows r0/r1

        // ---- pass 1: h0old against W0h (layer0) and Wlx (layer1) ----
#pragma unroll 1
        for (int ch = 0; ch < 4; ch++) {
#pragma unroll
            for (int j = 0; j < 4; j++) {
                const int idx = tid + j * 256;           // 1024 float4 slots
                const int rr = idx >> 5, cc = idx & 31;
                float4 v = __ldcg(reinterpret_cast<const float4*>(
                    h0old + (long long)(bg * 32 + rr) * HH + ch * 128 + cc * 4));
                *reinterpret_cast<float4*>(hs + rr * HSTR + cc * 4) = v;
            }
            __syncthreads();
            const float* w0r = sm + OFF_W0 + c_l * WSTR + ch * 128;
            const float* wxr = sm + OFF_WX + c_l * WSTR + ch * 128;
#pragma unroll 8
            for (int k4 = 0; k4 < 32; k4++) {
                const float4 ha = *reinterpret_cast<const float4*>(hs + r0 * HSTR + k4 * 4);
                const float4 hb = *reinterpret_cast<const float4*>(hs + r1 * HSTR + k4 * 4);
                const float4 w0 = *reinterpret_cast<const float4*>(w0r + k4 * 4);
                const float4 wx = *reinterpret_cast<const float4*>(wxr + k4 * 4);
                fma4(a00, ha, w0);
                fma4(a01, hb, w0);
                fma4(a10, ha, wx);
                fma4(a11, hb, wx);
            }
            __syncthreads();
        }

        // ---- pass 2: h1prev against Wlh (layer1) ----
#pragma unroll 1
        for (int ch = 0; ch < 4; ch++) {
#pragma unroll
            for (int j = 0; j < 4; j++) {
                const int idx = tid + j * 256;
                const int rr = idx >> 5, cc = idx & 31;
                float4 v = __ldcg(reinterpret_cast<const float4*>(
                    h1prev + (long long)(bg * 32 + rr) * HH + ch * 128 + cc * 4));
                *reinterpret_cast<float4*>(hs + rr * HSTR + cc * 4) = v;
            }
            __syncthreads();
            const float* wlr = sm + OFF_WL + c_l * WSTR + ch * 128;
#pragma unroll 8
            for (int k4 = 0; k4 < 32; k4++) {
                const float4 ha = *reinterpret_cast<const float4*>(hs + r0 * HSTR + k4 * 4);
                const float4 hb = *reinterpret_cast<const float4*>(hs + r1 * HSTR + k4 * 4);
                const float4 wv = *reinterpret_cast<const float4*>(wlr + k4 * 4);
                fma4(a10, ha, wv);
                fma4(a11, hb, wv);
            }
            __syncthreads();
        }

        // ---- epilogue ----
        if (p < SS) {  // layer0 output h0(p)
            const int t0 = inputs[p * BB + gb0];
            const int t1 = inputs[p * BB + gb1];
            const float s0 = (a00.x + a00.y) + (a00.z + a00.w);
            const float s1 = (a01.x + a01.y) + (a01.z + a01.w);
            h0new[gb0 * HH + col] = tanhf(s0 + g_P[t0 * HH + col] + b0c);
            h0new[gb1 * HH + col] = tanhf(s1 + g_P[t1 * HH + col] + b0c);
        }
        if (p >= 1) {  // layer1 output h1(p-1)
            const int s = p - 1;
            const float s0 = (a10.x + a10.y) + (a10.z + a10.w);
            const float s1 = (a11.x + a11.y) + (a11.z + a11.w);
            const float v0 = tanhf(s0 + blc);
            const float v1 = tanhf(s1 + blc);
            h1new[gb0 * HH + col] = v0;
            h1new[gb1 * HH + col] = v1;
            const long long o0 = ((long long)s * BB + gb0) * HH + col;
            const long long o1 = ((long long)s * BB + gb1) * HH + col;
            __nv_bfloat16 hv0 = __float2bfloat16(v0);
            __nv_bfloat16 hv1 = __float2bfloat16(v1);
            g_Thi[o0] = hv0; g_Tlo[o0] = __float2bfloat16(v0 - __bfloat162float(hv0));
            g_Thi[o1] = hv1; g_Tlo[o1] = __float2bfloat16(v1 - __bfloat162float(hv1));
        }

        if (p < SS) grid_bar((unsigned)(p + 1) * RNN_CTAS);
    }
}

// ---------------- prep kernels -----------------------------------------------
__global__ void prep_w0x(const float* __restrict__ W0) {
    int idx = blockIdx.x * blockDim.x + threadIdx.x;
    if (idx >= HH * EE) return;
    int c = idx / EE;     // output col (row of X)
    int e = idx % EE;
    float v = W0[c * (HH + EE) + HH + e];
    __nv_bfloat16 hi = __float2bfloat16(v);
    g_Xhi[c * EE + e] = hi;
    g_Xlo[c * EE + e] = __float2bfloat16(v - __bfloat162float(hi));
}

__global__ void split_arr(const float* __restrict__ src, __nv_bfloat16* __restrict__ hi,
                          __nv_bfloat16* __restrict__ lo, int n, float scale) {
    int i = blockIdx.x * blockDim.x + threadIdx.x;
    if (i >= n) return;
    float v = src[i] * scale;
    __nv_bfloat16 h = __float2bfloat16(v);
    hi[i] = h;
    lo[i] = __float2bfloat16(v - __bfloat162float(h));
}

__global__ void init_state(const float* __restrict__ hidden) {
    int i = blockIdx.x * blockDim.x + threadIdx.x;
    if (i == 0) g_sync = 0;
    if (i < BB * HH) {
        g_h0[1][i] = hidden[i];             // h0(-1) lives in buffer 1
        g_h1[1][i] = hidden[BB * HH + i];   // h1(-1) lives in buffer 1
    }
}

__global__ void write_hfinal(float* __restrict__ out) {
    int i = blockIdx.x * blockDim.x + threadIdx.x;
    if (i < BB * HH) {
        out[i] = g_h0[1][i];                // h0(127): phase 127 -> buf 1
        out[BB * HH + i] = g_h1[1][i];      // h1(127): phase 128 -> buf 1
    }
}

// ---------------- launch ------------------------------------------------------
extern "C" void kernel_launch(void* const* d_in, const int* in_sizes, int n_in,
                              void* d_out, int out_size) {
    const int*   inputs = (const int*)  d_in[0];
    const float* hidden = (const float*)d_in[1];
    const float* emb    = (const float*)d_in[2];
    const float* W0     = (const float*)d_in[3];
    const float* b0     = (const float*)d_in[4];
    const float* Wl     = (const float*)d_in[5];
    const float* bl     = (const float*)d_in[6];
    const float* Wout   = (const float*)d_in[7];
    const float* bout   = (const float*)d_in[8];

    float* logits = (float*)d_out;
    float* hfin   = (float*)d_out + (long long)SS * BB * VV;

    cudaFuncSetAttribute(gemm_hmma, cudaFuncAttributeMaxDynamicSharedMemorySize,
                         GEMM_SMEM);
    cudaFuncSetAttribute(rnn_persist, cudaFuncAttributeMaxDynamicSharedMemorySize,
                         RNN_SMEM);

    float* pP = nullptr;
    cudaGetSymbolAddress((void**)&pP, g_P);
    __nv_bfloat16 *pThi, *pTlo, *pWhi, *pWlo, *pEhi, *pElo, *pXhi, *pXlo;
    cudaGetSymbolAddress((void**)&pThi, g_Thi);
    cudaGetSymbolAddress((void**)&pTlo, g_Tlo);
    cudaGetSymbolAddress((void**)&pWhi, g_Whi);
    cudaGetSymbolAddress((void**)&pWlo, g_Wlo);
    cudaGetSymbolAddress((void**)&pEhi, g_Ehi);
    cudaGetSymbolAddress((void**)&pElo, g_Elo);
    cudaGetSymbolAddress((void**)&pXhi, g_Xhi);
    cudaGetSymbolAddress((void**)&pXlo, g_Xlo);

    const float scale = 22.62741699796952f;  // sqrt(512)

    // 1. prep
    init_state<<<(BB * HH + 255) / 256, 256>>>(hidden);
    prep_w0x<<<(HH * EE + 255) / 256, 256>>>(W0);
    split_arr<<<(VV * EE + 255) / 256, 256>>>(emb, pEhi, pElo, VV * EE, scale);
    split_arr<<<(VV * HH + 255) / 256, 256>>>(Wout, pWhi, pWlo, VV * HH, 1.0f);

    // 2. P = scale*emb @ W0x^T  (M=10000, N=512, K=512)
    {
        dim3 grid((HH + 127) / 128, (VV + 127) / 128);
        gemm_hmma<<<grid, 256, GEMM_SMEM>>>(pEhi, pElo, pXhi, pXlo,
                                            VV, HH, pP, HH, nullptr);
    }

    // 3. full recurrence in ONE persistent kernel
    rnn_persist<<<RNN_CTAS, RNN_THR, RNN_SMEM>>>(inputs, W0, b0, Wl, bl);

    // 4. logits = tops @ Wout^T + bout  (M=16384, N=10000, K=512)
    {
        dim3 grid((VV + 127) / 128, (SS * BB + 127) / 128);
        gemm_hmma<<<grid, 256, GEMM_SMEM>>>(pThi, pTlo, pWhi, pWlo,
                                            SS * BB, VV, logits, VV, bout);
    }

    // 5. final hidden state
    write_hfinal<<<(BB * HH + 255) / 256, 256>>>(hfin);
}